// round 1
// baseline (speedup 1.0000x reference)
#include <cuda_runtime.h>
#include <math.h>

// Problem constants (fixed shapes for JTNNEncoder_64836826301013)
#define MM 100001   // messages (+null slot 0)
#define NN 50000    // nodes
#define HH 256      // hidden
#define KK 6        // neighbors
#define BB 64       // trees
#define NDEPTH 6

// ---------------- device scratch (static; no allocations allowed) -----------
__device__ float g_x   [(size_t)MM * HH];        // x = emb[fnode[fmess]]
__device__ float g_x3  [(size_t)MM * 3 * HH];    // [xz | xr | xh] per message
__device__ float g_hUr [(size_t)MM * HH];
__device__ float g_sumh[(size_t)MM * HH];
__device__ float g_sumg[(size_t)MM * HH];
__device__ float g_zlin[(size_t)MM * HH];
__device__ float g_hlin[(size_t)MM * HH];
__device__ float g_Wpre[768 * 256];              // packed [Wz1; Wr; Wh1]
__device__ float g_Wz2 [256 * 256];
__device__ float g_Wh2 [256 * 256];

__device__ __forceinline__ float sigmf(float v) { return 1.0f / (1.0f + expf(-v)); }

// ---------------- pack weights into contiguous [out,256] matrices -----------
__global__ void k_pack(const float* __restrict__ Wz, const float* __restrict__ Wr,
                       const float* __restrict__ Wh) {
    int idx = blockIdx.x * blockDim.x + threadIdx.x;
    if (idx < 768 * 256) {
        int j = idx >> 8, i = idx & 255;
        float v;
        if (j < 256)      v = Wz[j * 512 + i];            // Wz[:, :H]
        else if (j < 512) v = Wr[(j - 256) * 256 + i];    // Wr
        else              v = Wh[(j - 512) * 512 + i];    // Wh[:, :H]
        g_Wpre[idx] = v;
    } else {
        int t = idx - 768 * 256;
        if (t < 2 * 65536) {
            int jj = (t >> 8) & 255, ii = t & 255;
            if (t < 65536) g_Wz2[t]          = Wz[jj * 512 + 256 + ii];
            else           g_Wh2[t - 65536]  = Wh[jj * 512 + 256 + ii];
        }
    }
}

// ---------------- x = emb[fnode[fmess]] -------------------------------------
__global__ void k_embed(const int* __restrict__ fnode, const int* __restrict__ fmess,
                        const float* __restrict__ emb) {
    int e = blockIdx.x * blockDim.x + threadIdx.x;   // one float4 per thread
    if (e >= MM * 64) return;
    int m = e >> 6;
    int c = (e & 63) * 4;
    int v = fnode[fmess[m]];
    *(float4*)(g_x + (size_t)m * HH + c) = *(const float4*)(emb + (size_t)v * HH + c);
}

// ---------------- generic fp32 GEMM: C[M,Nout] = A[M,256] @ W[Nout,256]^T ----
// A lda = 256, W ld = 256 (row-major, rows = output features). Nout = 128*gridDim.y.
#define GBM 128
#define GBN 128
#define GBK 8
__global__ __launch_bounds__(256, 2)
void k_gemm(const float* __restrict__ A, const float* __restrict__ W,
            float* __restrict__ C, int Mrows, int ldc) {
    __shared__ float As[GBK][GBM];
    __shared__ float Ws[GBK][GBN];
    int tid = threadIdx.x;
    int bm = blockIdx.x * GBM;
    int bn = blockIdx.y * GBN;
    int lrow = tid >> 1;             // 0..127
    int lcol = (tid & 1) * 4;        // 0 or 4
    int ty8 = (tid >> 4) * 8;        // 0..120
    int tx8 = (tid & 15) * 8;

    float acc[8][8];
#pragma unroll
    for (int i = 0; i < 8; i++)
#pragma unroll
        for (int j = 0; j < 8; j++) acc[i][j] = 0.0f;

    for (int k0 = 0; k0 < 256; k0 += GBK) {
        float4 av = make_float4(0.f, 0.f, 0.f, 0.f);
        int grow = bm + lrow;
        if (grow < Mrows)
            av = *(const float4*)(A + (size_t)grow * 256 + k0 + lcol);
        As[lcol + 0][lrow] = av.x; As[lcol + 1][lrow] = av.y;
        As[lcol + 2][lrow] = av.z; As[lcol + 3][lrow] = av.w;

        float4 wv = *(const float4*)(W + (size_t)(bn + lrow) * 256 + k0 + lcol);
        Ws[lcol + 0][lrow] = wv.x; Ws[lcol + 1][lrow] = wv.y;
        Ws[lcol + 2][lrow] = wv.z; Ws[lcol + 3][lrow] = wv.w;
        __syncthreads();

#pragma unroll
        for (int kk = 0; kk < GBK; kk++) {
            float4 a0 = *(const float4*)&As[kk][ty8];
            float4 a1 = *(const float4*)&As[kk][ty8 + 4];
            float4 b0 = *(const float4*)&Ws[kk][tx8];
            float4 b1 = *(const float4*)&Ws[kk][tx8 + 4];
            float a[8] = {a0.x, a0.y, a0.z, a0.w, a1.x, a1.y, a1.z, a1.w};
            float b[8] = {b0.x, b0.y, b0.z, b0.w, b1.x, b1.y, b1.z, b1.w};
#pragma unroll
            for (int i = 0; i < 8; i++)
#pragma unroll
                for (int j = 0; j < 8; j++) acc[i][j] = fmaf(a[i], b[j], acc[i][j]);
        }
        __syncthreads();
    }
#pragma unroll
    for (int i = 0; i < 8; i++) {
        int row = bm + ty8 + i;
        if (row < Mrows) {
            float* cp = C + (size_t)row * ldc + bn + tx8;
            *(float4*)cp       = make_float4(acc[i][0], acc[i][1], acc[i][2], acc[i][3]);
            *(float4*)(cp + 4) = make_float4(acc[i][4], acc[i][5], acc[i][6], acc[i][7]);
        }
    }
}

// ---------------- first GRU step (h == 0) -----------------------------------
__global__ void k_first(float* __restrict__ h, const float* __restrict__ bz,
                        const float* __restrict__ bh) {
    int e = blockIdx.x * blockDim.x + threadIdx.x;
    if (e >= MM * 64) return;
    int m = e >> 6;
    int c = (e & 63) * 4;
    float4 xz = *(const float4*)(g_x3 + (size_t)m * 768 + c);
    float4 xh = *(const float4*)(g_x3 + (size_t)m * 768 + 512 + c);
    float4 bzv = *(const float4*)(bz + c);
    float4 bhv = *(const float4*)(bh + c);
    float4 o;
    o.x = sigmf(xz.x + bzv.x) * tanhf(xh.x + bhv.x);
    o.y = sigmf(xz.y + bzv.y) * tanhf(xh.y + bhv.y);
    o.z = sigmf(xz.z + bzv.z) * tanhf(xh.z + bhv.z);
    o.w = sigmf(xz.w + bzv.w) * tanhf(xh.w + bhv.w);
    if (m == 0) o = make_float4(0.f, 0.f, 0.f, 0.f);
    *(float4*)(h + (size_t)m * HH + c) = o;
}

// ---------------- neighbor gather: sum_h and sum(r * h_nei) ------------------
__global__ void k_gather(const float* __restrict__ h, const int* __restrict__ mg,
                         const float* __restrict__ bu) {
    int m = blockIdx.x * blockDim.y + threadIdx.y;
    if (m >= MM) return;
    int c = threadIdx.x * 4;
    int idx[KK];
#pragma unroll
    for (int k = 0; k < KK; k++) idx[k] = mg[m * KK + k];
    float4 xr = *(const float4*)(g_x3 + (size_t)m * 768 + 256 + c);
    float4 bv = *(const float4*)(bu + c);
    float4 as = make_float4(0.f, 0.f, 0.f, 0.f);
    float4 ag = make_float4(0.f, 0.f, 0.f, 0.f);
#pragma unroll
    for (int k = 0; k < KK; k++) {
        const float4 hv = *(const float4*)(h + (size_t)idx[k] * HH + c);
        const float4 uv = *(const float4*)(g_hUr + (size_t)idx[k] * HH + c);
        float rx = sigmf(xr.x + uv.x + bv.x);
        float ry = sigmf(xr.y + uv.y + bv.y);
        float rz = sigmf(xr.z + uv.z + bv.z);
        float rw = sigmf(xr.w + uv.w + bv.w);
        as.x += hv.x; as.y += hv.y; as.z += hv.z; as.w += hv.w;
        ag.x = fmaf(rx, hv.x, ag.x); ag.y = fmaf(ry, hv.y, ag.y);
        ag.z = fmaf(rz, hv.z, ag.z); ag.w = fmaf(rw, hv.w, ag.w);
    }
    *(float4*)(g_sumh + (size_t)m * HH + c) = as;
    *(float4*)(g_sumg + (size_t)m * HH + c) = ag;
}

// ---------------- GRU update -------------------------------------------------
__global__ void k_update(float* __restrict__ h, const float* __restrict__ bz,
                         const float* __restrict__ bh) {
    int e = blockIdx.x * blockDim.x + threadIdx.x;
    if (e >= MM * 64) return;
    int m = e >> 6;
    int c = (e & 63) * 4;
    size_t o256 = (size_t)m * HH + c;
    float4 xz = *(const float4*)(g_x3 + (size_t)m * 768 + c);
    float4 xh = *(const float4*)(g_x3 + (size_t)m * 768 + 512 + c);
    float4 zl = *(const float4*)(g_zlin + o256);
    float4 hl = *(const float4*)(g_hlin + o256);
    float4 sh = *(const float4*)(g_sumh + o256);
    float4 sg = *(const float4*)(g_sumg + o256);
    float4 bzv = *(const float4*)(bz + c);
    float4 bhv = *(const float4*)(bh + c);
    float4 o;
    {
        float z = sigmf(xz.x + zl.x + bzv.x);
        float p = tanhf(xh.x + hl.x + bhv.x);
        o.x = (1.0f - z) * sh.x + z * p;
    }
    {
        float z = sigmf(xz.y + zl.y + bzv.y);
        float p = tanhf(xh.y + hl.y + bhv.y);
        o.y = (1.0f - z) * sh.y + z * p;
    }
    {
        float z = sigmf(xz.z + zl.z + bzv.z);
        float p = tanhf(xh.z + hl.z + bhv.z);
        o.z = (1.0f - z) * sh.z + z * p;
    }
    {
        float z = sigmf(xz.w + zl.w + bzv.w);
        float p = tanhf(xh.w + hl.w + bhv.w);
        o.w = (1.0f - z) * sh.w + z * p;
    }
    if (m == 0) o = make_float4(0.f, 0.f, 0.f, 0.f);
    *(float4*)(h + o256) = o;
}

// ---------------- readout: only the B=64 scope rows --------------------------
__global__ void k_readout(const int* __restrict__ scope_st, const int* __restrict__ fnode,
                          const int* __restrict__ node_graph, const float* __restrict__ emb,
                          const float* __restrict__ h, const float* __restrict__ Wo,
                          const float* __restrict__ bo, float* __restrict__ out) {
    __shared__ float fe[HH];
    __shared__ float mn[HH];
    int b = blockIdx.x;
    int j = threadIdx.x;
    int n = scope_st[b];
    fe[j] = emb[(size_t)fnode[n] * HH + j];
    float s = 0.0f;
#pragma unroll
    for (int k = 0; k < KK; k++) s += h[(size_t)node_graph[n * KK + k] * HH + j];
    mn[j] = s;
    __syncthreads();
    float acc = bo[j];
    const float* wrow = Wo + (size_t)j * 512;
#pragma unroll 4
    for (int i = 0; i < 256; i += 4) {
        float4 w = *(const float4*)(wrow + i);
        float4 f = *(const float4*)&fe[i];
        acc = fmaf(w.x, f.x, acc); acc = fmaf(w.y, f.y, acc);
        acc = fmaf(w.z, f.z, acc); acc = fmaf(w.w, f.w, acc);
    }
#pragma unroll 4
    for (int i = 0; i < 256; i += 4) {
        float4 w = *(const float4*)(wrow + 256 + i);
        float4 f = *(const float4*)&mn[i];
        acc = fmaf(w.x, f.x, acc); acc = fmaf(w.y, f.y, acc);
        acc = fmaf(w.z, f.z, acc); acc = fmaf(w.w, f.w, acc);
    }
    out[(size_t)b * HH + j] = fmaxf(acc, 0.0f);
}

// ---------------- launch ------------------------------------------------------
extern "C" void kernel_launch(void* const* d_in, const int* in_sizes, int n_in,
                              void* d_out, int out_size) {
    const int*   fnode      = (const int*)  d_in[0];
    const int*   fmess      = (const int*)  d_in[1];
    const int*   node_graph = (const int*)  d_in[2];
    const int*   mess_graph = (const int*)  d_in[3];
    const int*   scope_st   = (const int*)  d_in[4];
    const float* emb        = (const float*)d_in[5];
    const float* Wz         = (const float*)d_in[6];
    const float* bz         = (const float*)d_in[7];
    const float* Wr         = (const float*)d_in[8];
    const float* Ur         = (const float*)d_in[9];
    const float* bu         = (const float*)d_in[10];
    const float* Wh         = (const float*)d_in[11];
    const float* bh         = (const float*)d_in[12];
    const float* Wo         = (const float*)d_in[13];
    const float* bo         = (const float*)d_in[14];

    float* out = (float*)d_out;
    float* h = out + (size_t)BB * HH;   // h lives directly in the output buffer

    float *xptr, *x3ptr, *hUrptr, *sumhptr, *sumgptr, *zlinptr, *hlinptr;
    float *Wpreptr, *Wz2ptr, *Wh2ptr;
    cudaGetSymbolAddress((void**)&xptr,    g_x);
    cudaGetSymbolAddress((void**)&x3ptr,   g_x3);
    cudaGetSymbolAddress((void**)&hUrptr,  g_hUr);
    cudaGetSymbolAddress((void**)&sumhptr, g_sumh);
    cudaGetSymbolAddress((void**)&sumgptr, g_sumg);
    cudaGetSymbolAddress((void**)&zlinptr, g_zlin);
    cudaGetSymbolAddress((void**)&hlinptr, g_hlin);
    cudaGetSymbolAddress((void**)&Wpreptr, g_Wpre);
    cudaGetSymbolAddress((void**)&Wz2ptr,  g_Wz2);
    cudaGetSymbolAddress((void**)&Wh2ptr,  g_Wh2);

    const int ETHREADS = 256;
    const int EBLOCKS  = (MM * 64 + ETHREADS - 1) / ETHREADS;   // 25001
    const int MTILES   = (MM + GBM - 1) / GBM;                  // 782

    // pack weights + embed x
    k_pack <<<((768 * 256 + 2 * 65536) + 255) / 256, 256>>>(Wz, Wr, Wh);
    k_embed<<<EBLOCKS, ETHREADS>>>(fnode, fmess, emb);

    // x3 = x @ [Wz1; Wr; Wh1]^T   (M x 768)
    k_gemm<<<dim3(MTILES, 6), 256>>>(xptr, Wpreptr, x3ptr, MM, 768);

    // depth 0: h = sigmoid(xz+bz) * tanh(xh+bh) * mask
    k_first<<<EBLOCKS, ETHREADS>>>(h, bz, bh);

    // depths 1..5
    for (int it = 1; it < NDEPTH; it++) {
        k_gemm<<<dim3(MTILES, 2), 256>>>(h, Ur, hUrptr, MM, 256);          // hUr = h @ Ur^T
        k_gather<<<(MM + 3) / 4, dim3(64, 4)>>>(h, mess_graph, bu);        // sum_h, sum(r*h)
        k_gemm<<<dim3(MTILES, 2), 256>>>(sumhptr, Wz2ptr, zlinptr, MM, 256);
        k_gemm<<<dim3(MTILES, 2), 256>>>(sumgptr, Wh2ptr, hlinptr, MM, 256);
        k_update<<<EBLOCKS, ETHREADS>>>(h, bz, bh);
    }

    // tree_vecs from the 64 scope roots only
    k_readout<<<BB, HH>>>(scope_st, fnode, node_graph, emb, h, Wo, bo, out);
}

// round 2
// speedup vs baseline: 1.0581x; 1.0581x over previous
#include <cuda_runtime.h>
#include <math.h>

// Problem constants (fixed shapes for JTNNEncoder_64836826301013)
#define MM 100001   // messages (+null slot 0)
#define NN 50000    // nodes
#define HH 256      // hidden
#define KK 6        // neighbors
#define BB 64       // trees
#define NDEPTH 6

// ---------------- device scratch (static; no allocations allowed) -----------
__device__ float g_x   [(size_t)MM * HH];        // x = emb[fnode[fmess]]
__device__ float g_x3  [(size_t)MM * 3 * HH];    // [xz | xr | xh] per message
__device__ float g_hUr [(size_t)MM * HH];
__device__ float g_sumh[(size_t)MM * HH];
__device__ float g_sumg[(size_t)MM * HH];
__device__ float g_zlin[(size_t)MM * HH];
__device__ float g_Wpre[768 * 256];              // packed [Wz1; Wr; Wh1]
__device__ float g_Wz2 [256 * 256];
__device__ float g_Wh2 [256 * 256];

__device__ __forceinline__ float sigmf(float v) { return 1.0f / (1.0f + expf(-v)); }

// ---------------- pack weights into contiguous [out,256] matrices -----------
__global__ void k_pack(const float* __restrict__ Wz, const float* __restrict__ Wr,
                       const float* __restrict__ Wh) {
    int idx = blockIdx.x * blockDim.x + threadIdx.x;
    if (idx < 768 * 256) {
        int j = idx >> 8, i = idx & 255;
        float v;
        if (j < 256)      v = Wz[j * 512 + i];            // Wz[:, :H]
        else if (j < 512) v = Wr[(j - 256) * 256 + i];    // Wr
        else              v = Wh[(j - 512) * 512 + i];    // Wh[:, :H]
        g_Wpre[idx] = v;
    } else {
        int t = idx - 768 * 256;
        if (t < 2 * 65536) {
            int jj = (t >> 8) & 255, ii = t & 255;
            if (t < 65536) g_Wz2[t]          = Wz[jj * 512 + 256 + ii];
            else           g_Wh2[t - 65536]  = Wh[jj * 512 + 256 + ii];
        }
    }
}

// ---------------- x = emb[fnode[fmess]] -------------------------------------
__global__ void k_embed(const int* __restrict__ fnode, const int* __restrict__ fmess,
                        const float* __restrict__ emb) {
    int e = blockIdx.x * blockDim.x + threadIdx.x;   // one float4 per thread
    if (e >= MM * 64) return;
    int m = e >> 6;
    int c = (e & 63) * 4;
    int v = fnode[fmess[m]];
    *(float4*)(g_x + (size_t)m * HH + c) = *(const float4*)(emb + (size_t)v * HH + c);
}

// =============================================================================
// fp32 GEMM with packed f32x2 FMA: C[M,Nout] = A[M,256] @ W[Nout,256]^T
// 128x128 tile, GBK=16, 256 threads, 8x8 outputs per thread (as 8x4 f32x2).
// =============================================================================
#define GBM 128
#define GBN 128
#define GBK 16

// Shared GEMM mainloop producing 8x4 packed accumulators.
// After the call, acc2[i][j] holds cols (tx8+2j, tx8+2j+1) of row ty8+i.
__device__ __forceinline__ void gemm_mainloop(
    const float* __restrict__ A, const float* __restrict__ W,
    int Mrows, int bm, int bn, int ty8, int tx8,
    float (*As)[GBM], float (*Ws)[GBN],
    unsigned long long acc2[8][4])
{
    int tid = threadIdx.x;
    int lrow = tid >> 1;             // 0..127
    int lcol = (tid & 1) * 8;        // 0 or 8

#pragma unroll
    for (int i = 0; i < 8; i++)
#pragma unroll
        for (int j = 0; j < 4; j++) acc2[i][j] = 0ULL;

    for (int k0 = 0; k0 < 256; k0 += GBK) {
        int grow = bm + lrow;
#pragma unroll
        for (int p = 0; p < 2; p++) {
            int kc = lcol + p * 4;
            float4 av = make_float4(0.f, 0.f, 0.f, 0.f);
            if (grow < Mrows)
                av = *(const float4*)(A + (size_t)grow * 256 + k0 + kc);
            As[kc + 0][lrow] = av.x; As[kc + 1][lrow] = av.y;
            As[kc + 2][lrow] = av.z; As[kc + 3][lrow] = av.w;
            float4 wv = *(const float4*)(W + (size_t)(bn + lrow) * 256 + k0 + kc);
            Ws[kc + 0][lrow] = wv.x; Ws[kc + 1][lrow] = wv.y;
            Ws[kc + 2][lrow] = wv.z; Ws[kc + 3][lrow] = wv.w;
        }
        __syncthreads();

#pragma unroll
        for (int kk = 0; kk < GBK; kk++) {
            float4 a0 = *(const float4*)&As[kk][ty8];
            float4 a1 = *(const float4*)&As[kk][ty8 + 4];
            // read b as 4 packed f32x2 (16B-aligned shared loads)
            const unsigned long long* bp =
                (const unsigned long long*)&Ws[kk][tx8];
            unsigned long long b2[4] = {bp[0], bp[1], bp[2], bp[3]};
            float af[8] = {a0.x, a0.y, a0.z, a0.w, a1.x, a1.y, a1.z, a1.w};
#pragma unroll
            for (int i = 0; i < 8; i++) {
                unsigned long long a2;
                unsigned int au = __float_as_uint(af[i]);
                asm("mov.b64 %0, {%1, %1};" : "=l"(a2) : "r"(au));
#pragma unroll
                for (int j = 0; j < 4; j++)
                    asm("fma.rn.f32x2 %0, %1, %2, %0;"
                        : "+l"(acc2[i][j]) : "l"(a2), "l"(b2[j]));
            }
        }
        __syncthreads();
    }
}

__global__ __launch_bounds__(256, 2)
void k_gemm(const float* __restrict__ A, const float* __restrict__ W,
            float* __restrict__ C, int Mrows, int ldc) {
    __shared__ float As[GBK][GBM];
    __shared__ float Ws[GBK][GBN];
    int tid = threadIdx.x;
    int bm = blockIdx.x * GBM;
    int bn = blockIdx.y * GBN;
    int ty8 = (tid >> 4) * 8;
    int tx8 = (tid & 15) * 8;

    unsigned long long acc2[8][4];
    gemm_mainloop(A, W, Mrows, bm, bn, ty8, tx8, As, Ws, acc2);

#pragma unroll
    for (int i = 0; i < 8; i++) {
        int row = bm + ty8 + i;
        if (row < Mrows) {
            unsigned long long* cp =
                (unsigned long long*)(C + (size_t)row * ldc + bn + tx8);
            cp[0] = acc2[i][0]; cp[1] = acc2[i][1];
            cp[2] = acc2[i][2]; cp[3] = acc2[i][3];
        }
    }
}

// GEMM (A=sumg, W=Wh2) with the full GRU update fused into the epilogue:
//   hlin = acc;  z = sig(xz + zlin + bz);  p = tanh(xh + hlin + bh);
//   h = ((1-z)*sumh + z*p) * mask
__global__ __launch_bounds__(256, 2)
void k_gemm_update(const float* __restrict__ A, const float* __restrict__ W,
                   float* __restrict__ Hout,
                   const float* __restrict__ bz, const float* __restrict__ bh) {
    __shared__ float As[GBK][GBM];
    __shared__ float Ws[GBK][GBN];
    int tid = threadIdx.x;
    int bm = blockIdx.x * GBM;
    int bn = blockIdx.y * GBN;
    int ty8 = (tid >> 4) * 8;
    int tx8 = (tid & 15) * 8;

    unsigned long long acc2[8][4];
    gemm_mainloop(A, W, MM, bm, bn, ty8, tx8, As, Ws, acc2);

    int c0 = bn + tx8;
    float4 bz0 = *(const float4*)(bz + c0);
    float4 bz1 = *(const float4*)(bz + c0 + 4);
    float4 bh0 = *(const float4*)(bh + c0);
    float4 bh1 = *(const float4*)(bh + c0 + 4);
    float bzv[8] = {bz0.x, bz0.y, bz0.z, bz0.w, bz1.x, bz1.y, bz1.z, bz1.w};
    float bhv[8] = {bh0.x, bh0.y, bh0.z, bh0.w, bh1.x, bh1.y, bh1.z, bh1.w};

#pragma unroll
    for (int i = 0; i < 8; i++) {
        int row = bm + ty8 + i;
        if (row >= MM) continue;
        size_t o768 = (size_t)row * 768 + c0;
        size_t o256 = (size_t)row * 256 + c0;
        float4 xz0 = *(const float4*)(g_x3 + o768);
        float4 xz1 = *(const float4*)(g_x3 + o768 + 4);
        float4 xh0 = *(const float4*)(g_x3 + o768 + 512);
        float4 xh1 = *(const float4*)(g_x3 + o768 + 512 + 4);
        float4 zl0 = *(const float4*)(g_zlin + o256);
        float4 zl1 = *(const float4*)(g_zlin + o256 + 4);
        float4 sh0 = *(const float4*)(g_sumh + o256);
        float4 sh1 = *(const float4*)(g_sumh + o256 + 4);
        float xzv[8] = {xz0.x, xz0.y, xz0.z, xz0.w, xz1.x, xz1.y, xz1.z, xz1.w};
        float xhv[8] = {xh0.x, xh0.y, xh0.z, xh0.w, xh1.x, xh1.y, xh1.z, xh1.w};
        float zlv[8] = {zl0.x, zl0.y, zl0.z, zl0.w, zl1.x, zl1.y, zl1.z, zl1.w};
        float shv[8] = {sh0.x, sh0.y, sh0.z, sh0.w, sh1.x, sh1.y, sh1.z, sh1.w};
        float ov[8];
#pragma unroll
        for (int j = 0; j < 8; j++) {
            unsigned int lo, hi;
            asm("mov.b64 {%0, %1}, %2;" : "=r"(lo), "=r"(hi)
                : "l"(acc2[i][j >> 1]));
            float hl = __uint_as_float((j & 1) ? hi : lo);
            float z = sigmf(xzv[j] + zlv[j] + bzv[j]);
            float p = tanhf(xhv[j] + hl + bhv[j]);
            ov[j] = (1.0f - z) * shv[j] + z * p;
        }
        if (row == 0) {
#pragma unroll
            for (int j = 0; j < 8; j++) ov[j] = 0.0f;
        }
        float* hp = Hout + o256;
        *(float4*)hp       = make_float4(ov[0], ov[1], ov[2], ov[3]);
        *(float4*)(hp + 4) = make_float4(ov[4], ov[5], ov[6], ov[7]);
    }
}

// ---------------- first GRU step (h == 0) -----------------------------------
__global__ void k_first(float* __restrict__ h, const float* __restrict__ bz,
                        const float* __restrict__ bh) {
    int e = blockIdx.x * blockDim.x + threadIdx.x;
    if (e >= MM * 64) return;
    int m = e >> 6;
    int c = (e & 63) * 4;
    float4 xz = *(const float4*)(g_x3 + (size_t)m * 768 + c);
    float4 xh = *(const float4*)(g_x3 + (size_t)m * 768 + 512 + c);
    float4 bzv = *(const float4*)(bz + c);
    float4 bhv = *(const float4*)(bh + c);
    float4 o;
    o.x = sigmf(xz.x + bzv.x) * tanhf(xh.x + bhv.x);
    o.y = sigmf(xz.y + bzv.y) * tanhf(xh.y + bhv.y);
    o.z = sigmf(xz.z + bzv.z) * tanhf(xh.z + bhv.z);
    o.w = sigmf(xz.w + bzv.w) * tanhf(xh.w + bhv.w);
    if (m == 0) o = make_float4(0.f, 0.f, 0.f, 0.f);
    *(float4*)(h + (size_t)m * HH + c) = o;
}

// ---------------- neighbor gather: sum_h and sum(r * h_nei) ------------------
__global__ void k_gather(const float* __restrict__ h, const int* __restrict__ mg,
                         const float* __restrict__ bu) {
    int m = blockIdx.x * blockDim.y + threadIdx.y;
    if (m >= MM) return;
    int c = threadIdx.x * 4;
    int idx[KK];
#pragma unroll
    for (int k = 0; k < KK; k++) idx[k] = mg[m * KK + k];
    float4 xr = *(const float4*)(g_x3 + (size_t)m * 768 + 256 + c);
    float4 bv = *(const float4*)(bu + c);
    float4 as = make_float4(0.f, 0.f, 0.f, 0.f);
    float4 ag = make_float4(0.f, 0.f, 0.f, 0.f);
#pragma unroll
    for (int k = 0; k < KK; k++) {
        const float4 hv = *(const float4*)(h + (size_t)idx[k] * HH + c);
        const float4 uv = *(const float4*)(g_hUr + (size_t)idx[k] * HH + c);
        float rx = sigmf(xr.x + uv.x + bv.x);
        float ry = sigmf(xr.y + uv.y + bv.y);
        float rz = sigmf(xr.z + uv.z + bv.z);
        float rw = sigmf(xr.w + uv.w + bv.w);
        as.x += hv.x; as.y += hv.y; as.z += hv.z; as.w += hv.w;
        ag.x = fmaf(rx, hv.x, ag.x); ag.y = fmaf(ry, hv.y, ag.y);
        ag.z = fmaf(rz, hv.z, ag.z); ag.w = fmaf(rw, hv.w, ag.w);
    }
    *(float4*)(g_sumh + (size_t)m * HH + c) = as;
    *(float4*)(g_sumg + (size_t)m * HH + c) = ag;
}

// ---------------- readout: only the B=64 scope rows --------------------------
__global__ void k_readout(const int* __restrict__ scope_st, const int* __restrict__ fnode,
                          const int* __restrict__ node_graph, const float* __restrict__ emb,
                          const float* __restrict__ h, const float* __restrict__ Wo,
                          const float* __restrict__ bo, float* __restrict__ out) {
    __shared__ float fe[HH];
    __shared__ float mn[HH];
    int b = blockIdx.x;
    int j = threadIdx.x;
    int n = scope_st[b];
    fe[j] = emb[(size_t)fnode[n] * HH + j];
    float s = 0.0f;
#pragma unroll
    for (int k = 0; k < KK; k++) s += h[(size_t)node_graph[n * KK + k] * HH + j];
    mn[j] = s;
    __syncthreads();
    float acc = bo[j];
    const float* wrow = Wo + (size_t)j * 512;
#pragma unroll 4
    for (int i = 0; i < 256; i += 4) {
        float4 w = *(const float4*)(wrow + i);
        float4 f = *(const float4*)&fe[i];
        acc = fmaf(w.x, f.x, acc); acc = fmaf(w.y, f.y, acc);
        acc = fmaf(w.z, f.z, acc); acc = fmaf(w.w, f.w, acc);
    }
#pragma unroll 4
    for (int i = 0; i < 256; i += 4) {
        float4 w = *(const float4*)(wrow + 256 + i);
        float4 f = *(const float4*)&mn[i];
        acc = fmaf(w.x, f.x, acc); acc = fmaf(w.y, f.y, acc);
        acc = fmaf(w.z, f.z, acc); acc = fmaf(w.w, f.w, acc);
    }
    out[(size_t)b * HH + j] = fmaxf(acc, 0.0f);
}

// ---------------- launch ------------------------------------------------------
extern "C" void kernel_launch(void* const* d_in, const int* in_sizes, int n_in,
                              void* d_out, int out_size) {
    const int*   fnode      = (const int*)  d_in[0];
    const int*   fmess      = (const int*)  d_in[1];
    const int*   node_graph = (const int*)  d_in[2];
    const int*   mess_graph = (const int*)  d_in[3];
    const int*   scope_st   = (const int*)  d_in[4];
    const float* emb        = (const float*)d_in[5];
    const float* Wz         = (const float*)d_in[6];
    const float* bz         = (const float*)d_in[7];
    const float* Wr         = (const float*)d_in[8];
    const float* Ur         = (const float*)d_in[9];
    const float* bu         = (const float*)d_in[10];
    const float* Wh         = (const float*)d_in[11];
    const float* bh         = (const float*)d_in[12];
    const float* Wo         = (const float*)d_in[13];
    const float* bo         = (const float*)d_in[14];

    float* out = (float*)d_out;
    float* h = out + (size_t)BB * HH;   // h lives directly in the output buffer

    float *xptr, *x3ptr, *hUrptr, *sumhptr, *sumgptr, *zlinptr;
    float *Wpreptr, *Wz2ptr, *Wh2ptr;
    cudaGetSymbolAddress((void**)&xptr,    g_x);
    cudaGetSymbolAddress((void**)&x3ptr,   g_x3);
    cudaGetSymbolAddress((void**)&hUrptr,  g_hUr);
    cudaGetSymbolAddress((void**)&sumhptr, g_sumh);
    cudaGetSymbolAddress((void**)&sumgptr, g_sumg);
    cudaGetSymbolAddress((void**)&zlinptr, g_zlin);
    cudaGetSymbolAddress((void**)&Wpreptr, g_Wpre);
    cudaGetSymbolAddress((void**)&Wz2ptr,  g_Wz2);
    cudaGetSymbolAddress((void**)&Wh2ptr,  g_Wh2);

    const int ETHREADS = 256;
    const int EBLOCKS  = (MM * 64 + ETHREADS - 1) / ETHREADS;   // 25001
    const int MTILES   = (MM + GBM - 1) / GBM;                  // 782

    // pack weights + embed x
    k_pack <<<((768 * 256 + 2 * 65536) + 255) / 256, 256>>>(Wz, Wr, Wh);
    k_embed<<<EBLOCKS, ETHREADS>>>(fnode, fmess, emb);

    // x3 = x @ [Wz1; Wr; Wh1]^T   (M x 768)
    k_gemm<<<dim3(MTILES, 6), 256>>>(xptr, Wpreptr, x3ptr, MM, 768);

    // depth 0: h = sigmoid(xz+bz) * tanh(xh+bh) * mask
    k_first<<<EBLOCKS, ETHREADS>>>(h, bz, bh);

    // depths 1..5
    for (int it = 1; it < NDEPTH; it++) {
        k_gemm<<<dim3(MTILES, 2), 256>>>(h, Ur, hUrptr, MM, 256);          // hUr = h @ Ur^T
        k_gather<<<(MM + 3) / 4, dim3(64, 4)>>>(h, mess_graph, bu);        // sum_h, sum(r*h)
        k_gemm<<<dim3(MTILES, 2), 256>>>(sumhptr, Wz2ptr, zlinptr, MM, 256);
        k_gemm_update<<<dim3(MTILES, 2), 256>>>(sumgptr, Wh2ptr, h, bz, bh);
    }

    // tree_vecs from the 64 scope roots only
    k_readout<<<BB, HH>>>(scope_st, fnode, node_graph, emb, h, Wo, bo, out);
}

// round 4
// speedup vs baseline: 1.8008x; 1.7020x over previous
#include <cuda_runtime.h>
#include <cuda_bf16.h>
#include <math.h>
#include <stdint.h>

#define MM 100001
#define NN 50000
#define HH 256
#define KK 6
#define BB 64
#define NDEPTH 6

// ---------------------------------------------------------------------------
// scratch (static; no allocations)
// ---------------------------------------------------------------------------
__device__ __align__(16) unsigned short g_xhi[(size_t)MM * HH];
__device__ __align__(16) unsigned short g_xlo[(size_t)MM * HH];
__device__ __align__(16) unsigned short g_hhi[(size_t)MM * HH];
__device__ __align__(16) unsigned short g_hlo[(size_t)MM * HH];
__device__ __align__(16) unsigned short g_shhi[(size_t)MM * HH];
__device__ __align__(16) unsigned short g_shlo[(size_t)MM * HH];
__device__ __align__(16) unsigned short g_sghi[(size_t)MM * HH];
__device__ __align__(16) unsigned short g_sglo[(size_t)MM * HH];
__device__ float g_x3   [(size_t)MM * 3 * HH];
__device__ float g_hUr  [(size_t)MM * HH];
__device__ float g_zlin [(size_t)MM * HH];
__device__ float g_sumhf[(size_t)MM * HH];
__device__ __align__(16) unsigned short g_Wprehi[768 * 256];
__device__ __align__(16) unsigned short g_Wprelo[768 * 256];
__device__ __align__(16) unsigned short g_Wz2hi[256 * 256];
__device__ __align__(16) unsigned short g_Wz2lo[256 * 256];
__device__ __align__(16) unsigned short g_Wh2hi[256 * 256];
__device__ __align__(16) unsigned short g_Wh2lo[256 * 256];
__device__ __align__(16) unsigned short g_Urhi[256 * 256];
__device__ __align__(16) unsigned short g_Urlo[256 * 256];

__device__ __forceinline__ float sigmf(float v) { return 1.0f / (1.0f + expf(-v)); }
__device__ __forceinline__ void split_bf(float v, unsigned short& hi, unsigned short& lo) {
    __nv_bfloat16 h = __float2bfloat16(v);
    __nv_bfloat16 l = __float2bfloat16(v - __bfloat162float(h));
    hi = *(unsigned short*)&h; lo = *(unsigned short*)&l;
}
struct us2 { unsigned short x, y; };
struct us4 { unsigned short x, y, z, w; };

__device__ __forceinline__ uint32_t smem_u32(const void* p) {
    uint32_t a;
    asm("{ .reg .u64 t; cvta.to.shared.u64 t, %1; cvt.u32.u64 %0, t; }" : "=r"(a) : "l"(p));
    return a;
}
__device__ __forceinline__ void ldsm4(uint32_t* r, uint32_t addr) {
    asm volatile("ldmatrix.sync.aligned.m8n8.x4.shared.b16 {%0,%1,%2,%3}, [%4];"
        : "=r"(r[0]), "=r"(r[1]), "=r"(r[2]), "=r"(r[3]) : "r"(addr));
}
__device__ __forceinline__ void mma16816(float* d, const uint32_t* a, const uint32_t* b) {
    asm volatile("mma.sync.aligned.m16n8k16.row.col.f32.bf16.bf16.f32 "
        "{%0,%1,%2,%3}, {%4,%5,%6,%7}, {%8,%9}, {%0,%1,%2,%3};"
        : "+f"(d[0]), "+f"(d[1]), "+f"(d[2]), "+f"(d[3])
        : "r"(a[0]), "r"(a[1]), "r"(a[2]), "r"(a[3]), "r"(b[0]), "r"(b[1]));
}

// ---------------------------------------------------------------------------
// weight pack + split
// ---------------------------------------------------------------------------
__global__ void k_pack(const float* __restrict__ Wz, const float* __restrict__ Wr,
                       const float* __restrict__ Wh, const float* __restrict__ Ur) {
    int idx = blockIdx.x * blockDim.x + threadIdx.x;
    int j = idx >> 8, i = idx & 255;
    float v; unsigned short hi, lo;
    if (j < 256)       v = Wz[j * 512 + i];
    else if (j < 512)  v = Wr[(j - 256) * 256 + i];
    else if (j < 768)  v = Wh[(j - 512) * 512 + i];
    else if (j < 1024) v = Wz[(j - 768) * 512 + 256 + i];
    else if (j < 1280) v = Wh[(j - 1024) * 512 + 256 + i];
    else               v = Ur[(j - 1280) * 256 + i];
    split_bf(v, hi, lo);
    if (j < 768)        { g_Wprehi[j * 256 + i] = hi;          g_Wprelo[j * 256 + i] = lo; }
    else if (j < 1024)  { g_Wz2hi[(j - 768) * 256 + i] = hi;   g_Wz2lo[(j - 768) * 256 + i] = lo; }
    else if (j < 1280)  { g_Wh2hi[(j - 1024) * 256 + i] = hi;  g_Wh2lo[(j - 1024) * 256 + i] = lo; }
    else                { g_Urhi[(j - 1280) * 256 + i] = hi;   g_Urlo[(j - 1280) * 256 + i] = lo; }
}

// ---------------------------------------------------------------------------
// embed
// ---------------------------------------------------------------------------
__global__ void k_embed(const int* __restrict__ fnode, const int* __restrict__ fmess,
                        const float* __restrict__ emb) {
    int e = blockIdx.x * blockDim.x + threadIdx.x;
    if (e >= MM * 64) return;
    int m = e >> 6, c = (e & 63) * 4;
    int v = fnode[fmess[m]];
    float4 f = *(const float4*)(emb + (size_t)v * HH + c);
    us4 hi, lo;
    split_bf(f.x, hi.x, lo.x); split_bf(f.y, hi.y, lo.y);
    split_bf(f.z, hi.z, lo.z); split_bf(f.w, hi.w, lo.w);
    *(us4*)(g_xhi + (size_t)m * HH + c) = hi;
    *(us4*)(g_xlo + (size_t)m * HH + c) = lo;
}

// ===========================================================================
// split-bf16 mma.sync GEMM: C[M,Nout] = A[M,256] @ W[Nout,256]^T
// CTA tile 128x128, 8 warps (4 in M x 2 in N), warp tile 32x64.
// smem stage: k_chunk=32, rows stride 80B (conflict-free ldmatrix),
// layout per stage: [A_hi | A_lo | B_hi | B_lo] each 128 rows x 80B.
// ===========================================================================
#define STG 40960
#define SMEM_GEMM (2 * STG)

__device__ __forceinline__ void issue_stage(
    uint32_t sb, const unsigned short* __restrict__ Ahi, const unsigned short* __restrict__ Alo,
    const unsigned short* __restrict__ Bhi, const unsigned short* __restrict__ Blo,
    int bm, int bn, int kc)
{
    int tid = threadIdx.x;
#pragma unroll
    for (int i = 0; i < 4; i++) {           // A planes: 1024 vec16
        int v = tid + i * 256;
        int plane = v >> 9, w = v & 511;
        int rr = w >> 2, cc = w & 3;
        int row = bm + rr;
        int sz = (row < MM) ? 16 : 0;
        const unsigned short* src = (plane ? Alo : Ahi) +
            (size_t)(row < MM ? row : MM - 1) * 256 + kc + cc * 8;
        uint32_t dst = sb + plane * 10240 + rr * 80 + cc * 16;
        asm volatile("cp.async.cg.shared.global [%0], [%1], 16, %2;"
                     :: "r"(dst), "l"(src), "r"(sz));
    }
#pragma unroll
    for (int i = 0; i < 4; i++) {           // B planes
        int v = tid + i * 256;
        int plane = v >> 9, w = v & 511;
        int rr = w >> 2, cc = w & 3;
        const unsigned short* src = (plane ? Blo : Bhi) + (size_t)(bn + rr) * 256 + kc + cc * 8;
        uint32_t dst = sb + 20480 + plane * 10240 + rr * 80 + cc * 16;
        asm volatile("cp.async.cg.shared.global [%0], [%1], 16, %2;"
                     :: "r"(dst), "l"(src), "r"(16));
    }
    asm volatile("cp.async.commit_group;" ::: "memory");
}

__device__ __forceinline__ void compute_stage(uint32_t sb, int warp_m, int warp_n,
                                              int lane, float acc[2][8][4]) {
    int quad = lane >> 3, lr = lane & 7;
    int rowA = ((quad & 1) << 3) + lr;
    int colA = (quad & 2) ? 8 : 0;
    int rowB = ((quad >> 1) << 3) + lr;
    int colB = (quad & 1) ? 8 : 0;
#pragma unroll
    for (int step = 0; step < 2; step++) {
        int kb = step * 16;
        uint32_t ahi[2][4], alo[2][4], bhi[8][2], blo[8][2];
#pragma unroll
        for (int mt = 0; mt < 2; mt++) {
            uint32_t ah = sb + (warp_m * 32 + mt * 16 + rowA) * 80 + (kb + colA) * 2;
            ldsm4(ahi[mt], ah);
            ldsm4(alo[mt], ah + 10240);
        }
#pragma unroll
        for (int np = 0; np < 4; np++) {
            uint32_t bh = sb + 20480 + (warp_n * 64 + np * 16 + rowB) * 80 + (kb + colB) * 2;
            uint32_t r[4];
            ldsm4(r, bh);
            bhi[np * 2][0] = r[0]; bhi[np * 2][1] = r[1];
            bhi[np * 2 + 1][0] = r[2]; bhi[np * 2 + 1][1] = r[3];
            ldsm4(r, bh + 10240);
            blo[np * 2][0] = r[0]; blo[np * 2][1] = r[1];
            blo[np * 2 + 1][0] = r[2]; blo[np * 2 + 1][1] = r[3];
        }
#pragma unroll
        for (int mt = 0; mt < 2; mt++)
#pragma unroll
            for (int nt = 0; nt < 8; nt++) {
                mma16816(acc[mt][nt], ahi[mt], bhi[nt]);
                mma16816(acc[mt][nt], alo[mt], bhi[nt]);
                mma16816(acc[mt][nt], ahi[mt], blo[nt]);
            }
    }
}

__device__ __forceinline__ void gemm_main(
    char* smc, const unsigned short* Ahi, const unsigned short* Alo,
    const unsigned short* Whi, const unsigned short* Wlo,
    int bm, int bn, float acc[2][8][4])
{
#pragma unroll
    for (int a = 0; a < 2; a++)
#pragma unroll
        for (int b = 0; b < 8; b++)
#pragma unroll
            for (int c = 0; c < 4; c++) acc[a][b][c] = 0.0f;

    uint32_t sb = smem_u32(smc);
    int lane = threadIdx.x & 31, wid = threadIdx.x >> 5;
    int warp_m = wid & 3, warp_n = wid >> 2;

    issue_stage(sb, Ahi, Alo, Whi, Wlo, bm, bn, 0);
    for (int s = 0; s < 8; s++) {
        if (s < 7) {
            issue_stage(sb + ((s + 1) & 1) * STG, Ahi, Alo, Whi, Wlo, bm, bn, (s + 1) * 32);
            asm volatile("cp.async.wait_group 1;" ::: "memory");
        } else {
            asm volatile("cp.async.wait_group 0;" ::: "memory");
        }
        __syncthreads();
        compute_stage(sb + (s & 1) * STG, warp_m, warp_n, lane, acc);
        __syncthreads();
    }
}

__global__ __launch_bounds__(256)
void k_gemm_f32(const unsigned short* __restrict__ Ahi, const unsigned short* __restrict__ Alo,
                const unsigned short* __restrict__ Whi, const unsigned short* __restrict__ Wlo,
                float* __restrict__ C, int ldc) {
    extern __shared__ char smc[];
    int bm = blockIdx.x * 128, bn = blockIdx.y * 128;
    float acc[2][8][4];
    gemm_main(smc, Ahi, Alo, Whi, Wlo, bm, bn, acc);
    int lane = threadIdx.x & 31, wid = threadIdx.x >> 5;
    int g = lane >> 2, tig = lane & 3;
#pragma unroll
    for (int mt = 0; mt < 2; mt++) {
        int row0 = bm + (wid & 3) * 32 + mt * 16 + g;
#pragma unroll
        for (int nt = 0; nt < 8; nt++) {
            int col = bn + (wid >> 2) * 64 + nt * 8 + tig * 2;
            if (row0 < MM)
                *(float2*)(C + (size_t)row0 * ldc + col) =
                    make_float2(acc[mt][nt][0], acc[mt][nt][1]);
            if (row0 + 8 < MM)
                *(float2*)(C + (size_t)(row0 + 8) * ldc + col) =
                    make_float2(acc[mt][nt][2], acc[mt][nt][3]);
        }
    }
}

// GRU fused epilogue for the sumg @ Wh2^T GEMM
__device__ __forceinline__ void gru2(int row, int col, float a0, float a1,
                                     const float* __restrict__ bz,
                                     const float* __restrict__ bh,
                                     float* __restrict__ Hout) {
    if (row >= MM) return;
    size_t o768 = (size_t)row * 768 + col;
    size_t o256 = (size_t)row * 256 + col;
    float2 xz = *(const float2*)(g_x3 + o768);
    float2 xh = *(const float2*)(g_x3 + o768 + 512);
    float2 zl = *(const float2*)(g_zlin + o256);
    float2 sh = *(const float2*)(g_sumhf + o256);
    float2 bzv = *(const float2*)(bz + col);
    float2 bhv = *(const float2*)(bh + col);
    float z0 = sigmf(xz.x + zl.x + bzv.x);
    float p0 = tanhf(xh.x + a0 + bhv.x);
    float o0 = (1.0f - z0) * sh.x + z0 * p0;
    float z1 = sigmf(xz.y + zl.y + bzv.y);
    float p1 = tanhf(xh.y + a1 + bhv.y);
    float o1 = (1.0f - z1) * sh.y + z1 * p1;
    if (row == 0) { o0 = 0.0f; o1 = 0.0f; }
    *(float2*)(Hout + o256) = make_float2(o0, o1);
    us2 hi, lo;
    split_bf(o0, hi.x, lo.x); split_bf(o1, hi.y, lo.y);
    *(us2*)(g_hhi + o256) = hi;
    *(us2*)(g_hlo + o256) = lo;
}

__global__ __launch_bounds__(256)
void k_gemm_gru(const unsigned short* __restrict__ Ahi, const unsigned short* __restrict__ Alo,
                const unsigned short* __restrict__ Whi, const unsigned short* __restrict__ Wlo,
                float* __restrict__ Hout, const float* __restrict__ bz,
                const float* __restrict__ bh) {
    extern __shared__ char smc[];
    int bm = blockIdx.x * 128, bn = blockIdx.y * 128;
    float acc[2][8][4];
    gemm_main(smc, Ahi, Alo, Whi, Wlo, bm, bn, acc);
    int lane = threadIdx.x & 31, wid = threadIdx.x >> 5;
    int g = lane >> 2, tig = lane & 3;
#pragma unroll
    for (int mt = 0; mt < 2; mt++) {
        int row0 = bm + (wid & 3) * 32 + mt * 16 + g;
#pragma unroll
        for (int nt = 0; nt < 8; nt++) {
            int col = bn + (wid >> 2) * 64 + nt * 8 + tig * 2;
            gru2(row0, col, acc[mt][nt][0], acc[mt][nt][1], bz, bh, Hout);
            gru2(row0 + 8, col, acc[mt][nt][2], acc[mt][nt][3], bz, bh, Hout);
        }
    }
}

// ---------------------------------------------------------------------------
// first GRU step (h == 0)
// ---------------------------------------------------------------------------
__global__ void k_first(float* __restrict__ h, const float* __restrict__ bz,
                        const float* __restrict__ bh) {
    int e = blockIdx.x * blockDim.x + threadIdx.x;
    if (e >= MM * 64) return;
    int m = e >> 6, c = (e & 63) * 4;
    float4 xz = *(const float4*)(g_x3 + (size_t)m * 768 + c);
    float4 xh = *(const float4*)(g_x3 + (size_t)m * 768 + 512 + c);
    float4 bzv = *(const float4*)(bz + c);
    float4 bhv = *(const float4*)(bh + c);
    float4 o;
    o.x = sigmf(xz.x + bzv.x) * tanhf(xh.x + bhv.x);
    o.y = sigmf(xz.y + bzv.y) * tanhf(xh.y + bhv.y);
    o.z = sigmf(xz.z + bzv.z) * tanhf(xh.z + bhv.z);
    o.w = sigmf(xz.w + bzv.w) * tanhf(xh.w + bhv.w);
    if (m == 0) o = make_float4(0.f, 0.f, 0.f, 0.f);
    *(float4*)(h + (size_t)m * HH + c) = o;
    us4 hi, lo;
    split_bf(o.x, hi.x, lo.x); split_bf(o.y, hi.y, lo.y);
    split_bf(o.z, hi.z, lo.z); split_bf(o.w, hi.w, lo.w);
    *(us4*)(g_hhi + (size_t)m * HH + c) = hi;
    *(us4*)(g_hlo + (size_t)m * HH + c) = lo;
}

// ---------------------------------------------------------------------------
// gather: sum_h (fp32 + planes) and sum(r*h_nei) (planes)
// ---------------------------------------------------------------------------
__global__ void k_gather(const float* __restrict__ h, const int* __restrict__ mg,
                         const float* __restrict__ bu) {
    int m = blockIdx.x * blockDim.y + threadIdx.y;
    if (m >= MM) return;
    int c = threadIdx.x * 4;
    int idx[KK];
#pragma unroll
    for (int k = 0; k < KK; k++) idx[k] = mg[m * KK + k];
    float4 xr = *(const float4*)(g_x3 + (size_t)m * 768 + 256 + c);
    float4 bv = *(const float4*)(bu + c);
    float4 as = make_float4(0.f, 0.f, 0.f, 0.f);
    float4 ag = make_float4(0.f, 0.f, 0.f, 0.f);
#pragma unroll
    for (int k = 0; k < KK; k++) {
        const float4 hv = *(const float4*)(h + (size_t)idx[k] * HH + c);
        const float4 uv = *(const float4*)(g_hUr + (size_t)idx[k] * HH + c);
        float rx = sigmf(xr.x + uv.x + bv.x);
        float ry = sigmf(xr.y + uv.y + bv.y);
        float rz = sigmf(xr.z + uv.z + bv.z);
        float rw = sigmf(xr.w + uv.w + bv.w);
        as.x += hv.x; as.y += hv.y; as.z += hv.z; as.w += hv.w;
        ag.x = fmaf(rx, hv.x, ag.x); ag.y = fmaf(ry, hv.y, ag.y);
        ag.z = fmaf(rz, hv.z, ag.z); ag.w = fmaf(rw, hv.w, ag.w);
    }
    *(float4*)(g_sumhf + (size_t)m * HH + c) = as;
    us4 hi, lo;
    split_bf(as.x, hi.x, lo.x); split_bf(as.y, hi.y, lo.y);
    split_bf(as.z, hi.z, lo.z); split_bf(as.w, hi.w, lo.w);
    *(us4*)(g_shhi + (size_t)m * HH + c) = hi;
    *(us4*)(g_shlo + (size_t)m * HH + c) = lo;
    split_bf(ag.x, hi.x, lo.x); split_bf(ag.y, hi.y, lo.y);
    split_bf(ag.z, hi.z, lo.z); split_bf(ag.w, hi.w, lo.w);
    *(us4*)(g_sghi + (size_t)m * HH + c) = hi;
    *(us4*)(g_sglo + (size_t)m * HH + c) = lo;
}

// ---------------------------------------------------------------------------
// readout (B=64 roots)
// ---------------------------------------------------------------------------
__global__ void k_readout(const int* __restrict__ scope_st, const int* __restrict__ fnode,
                          const int* __restrict__ node_graph, const float* __restrict__ emb,
                          const float* __restrict__ h, const float* __restrict__ Wo,
                          const float* __restrict__ bo, float* __restrict__ out) {
    __shared__ float fe[HH];
    __shared__ float mn[HH];
    int b = blockIdx.x, j = threadIdx.x;
    int n = scope_st[b];
    fe[j] = emb[(size_t)fnode[n] * HH + j];
    float s = 0.0f;
#pragma unroll
    for (int k = 0; k < KK; k++) s += h[(size_t)node_graph[n * KK + k] * HH + j];
    mn[j] = s;
    __syncthreads();
    float acc = bo[j];
    const float* wrow = Wo + (size_t)j * 512;
#pragma unroll 4
    for (int i = 0; i < 256; i += 4) {
        float4 w = *(const float4*)(wrow + i);
        float4 f = *(const float4*)&fe[i];
        acc = fmaf(w.x, f.x, acc); acc = fmaf(w.y, f.y, acc);
        acc = fmaf(w.z, f.z, acc); acc = fmaf(w.w, f.w, acc);
    }
#pragma unroll 4
    for (int i = 0; i < 256; i += 4) {
        float4 w = *(const float4*)(wrow + 256 + i);
        float4 f = *(const float4*)&mn[i];
        acc = fmaf(w.x, f.x, acc); acc = fmaf(w.y, f.y, acc);
        acc = fmaf(w.z, f.z, acc); acc = fmaf(w.w, f.w, acc);
    }
    out[(size_t)b * HH + j] = fmaxf(acc, 0.0f);
}

// ---------------------------------------------------------------------------
// launch
// ---------------------------------------------------------------------------
extern "C" void kernel_launch(void* const* d_in, const int* in_sizes, int n_in,
                              void* d_out, int out_size) {
    const int*   fnode      = (const int*)  d_in[0];
    const int*   fmess      = (const int*)  d_in[1];
    const int*   node_graph = (const int*)  d_in[2];
    const int*   mess_graph = (const int*)  d_in[3];
    const int*   scope_st   = (const int*)  d_in[4];
    const float* emb        = (const float*)d_in[5];
    const float* Wz         = (const float*)d_in[6];
    const float* bz         = (const float*)d_in[7];
    const float* Wr         = (const float*)d_in[8];
    const float* Ur         = (const float*)d_in[9];
    const float* bu         = (const float*)d_in[10];
    const float* Wh         = (const float*)d_in[11];
    const float* bh         = (const float*)d_in[12];
    const float* Wo         = (const float*)d_in[13];
    const float* bo         = (const float*)d_in[14];

    float* out = (float*)d_out;
    float* h = out + (size_t)BB * HH;

    cudaFuncSetAttribute(k_gemm_f32, cudaFuncAttributeMaxDynamicSharedMemorySize, SMEM_GEMM);
    cudaFuncSetAttribute(k_gemm_gru, cudaFuncAttributeMaxDynamicSharedMemorySize, SMEM_GEMM);

    unsigned short *xhi, *xlo, *hhi, *hlo, *shhi, *shlo, *sghi, *sglo;
    unsigned short *Wprehi, *Wprelo, *Wz2hi, *Wz2lo, *Wh2hi, *Wh2lo, *Urhi, *Urlo;
    float *x3p, *hUrp, *zlinp;
    cudaGetSymbolAddress((void**)&xhi, g_xhi);   cudaGetSymbolAddress((void**)&xlo, g_xlo);
    cudaGetSymbolAddress((void**)&hhi, g_hhi);   cudaGetSymbolAddress((void**)&hlo, g_hlo);
    cudaGetSymbolAddress((void**)&shhi, g_shhi); cudaGetSymbolAddress((void**)&shlo, g_shlo);
    cudaGetSymbolAddress((void**)&sghi, g_sghi); cudaGetSymbolAddress((void**)&sglo, g_sglo);
    cudaGetSymbolAddress((void**)&Wprehi, g_Wprehi); cudaGetSymbolAddress((void**)&Wprelo, g_Wprelo);
    cudaGetSymbolAddress((void**)&Wz2hi, g_Wz2hi);   cudaGetSymbolAddress((void**)&Wz2lo, g_Wz2lo);
    cudaGetSymbolAddress((void**)&Wh2hi, g_Wh2hi);   cudaGetSymbolAddress((void**)&Wh2lo, g_Wh2lo);
    cudaGetSymbolAddress((void**)&Urhi, g_Urhi);     cudaGetSymbolAddress((void**)&Urlo, g_Urlo);
    cudaGetSymbolAddress((void**)&x3p, g_x3);
    cudaGetSymbolAddress((void**)&hUrp, g_hUr);
    cudaGetSymbolAddress((void**)&zlinp, g_zlin);

    const int ETH = 256;
    const int EBL = (MM * 64 + ETH - 1) / ETH;
    const int MT  = (MM + 127) / 128;    // 782

    k_pack <<<1536, 256>>>(Wz, Wr, Wh, Ur);
    k_embed<<<EBL, ETH>>>(fnode, fmess, emb);

    // x3 = x @ [Wz1; Wr; Wh1]^T
    k_gemm_f32<<<dim3(MT, 6), 256, SMEM_GEMM>>>(xhi, xlo, Wprehi, Wprelo, x3p, 768);
    k_first<<<EBL, ETH>>>(h, bz, bh);

    for (int it = 1; it < NDEPTH; it++) {
        k_gemm_f32<<<dim3(MT, 2), 256, SMEM_GEMM>>>(hhi, hlo, Urhi, Urlo, hUrp, 256);
        k_gather<<<(MM + 3) / 4, dim3(64, 4)>>>(h, mess_graph, bu);
        k_gemm_f32<<<dim3(MT, 2), 256, SMEM_GEMM>>>(shhi, shlo, Wz2hi, Wz2lo, zlinp, 256);
        k_gemm_gru<<<dim3(MT, 2), 256, SMEM_GEMM>>>(sghi, sglo, Wh2hi, Wh2lo, h, bz, bh);
    }

    k_readout<<<BB, HH>>>(scope_st, fnode, node_graph, emb, h, Wo, bo, out);
}